// round 6
// baseline (speedup 1.0000x reference)
#include <cuda_runtime.h>
#include <math.h>

#define B   32
#define T0  16384
#define T1  8192
#define T2  4096
#define H   32
#define H2  64
#define ZD  64
#define KCB 1024

// ---------------- scratch (device globals; no runtime alloc) ----------------
__device__ float g_h1[B*H*T1];        // after conv1+lrelu   [b][32][8192]
__device__ float g_h2[B*H2*T2];       // after conv2+lrelu   [b][64][4096]
__device__ float g_z [B*ZD*T2];       // after conv3         [b][64][4096]
__device__ float g_quant[B*ZD*T2];    // q_st for decoder    [b][64][4096]
__device__ int   g_idx[B*T2];         // argmin indices
__device__ float g_d1[B*H2*T1];       // after deconv1+lrelu [b][64][8192]
__device__ float g_d2[B*H*T0];        // after deconv2+lrelu [b][32][16384]
__device__ float g_cn[KCB];           // codebook squared norms
__device__ float g_zn[B*T2];          // z row norms
__device__ float g_part[32768];       // loss partial sums

__device__ __forceinline__ float lrelu(float v){ return v > 0.f ? v : 0.2f*v; }

// XLA row-reduce warp tree: partial -> shfl_down 16/8/4/2/1, result in lane 0.
__device__ __forceinline__ float warp_tree_sum(float p){
    #pragma unroll
    for (int off = 16; off > 0; off >>= 1)
        p = __fadd_rn(p, __shfl_down_sync(0xFFFFFFFFu, p, off));
    return p;
}

// ---------------- conv1: 1->32, K=15, stride 2, pad 7 (fp32) ----------------
__global__ void k_conv1(const float* __restrict__ x, const float* __restrict__ w,
                        const float* __restrict__ bias){
    __shared__ float sw[H*15];
    __shared__ float sb[H];
    int tid = threadIdx.x;
    for (int i = tid; i < H*15; i += blockDim.x) sw[i] = w[i];
    if (tid < H) sb[tid] = bias[tid];
    __syncthreads();
    int g = blockIdx.x*blockDim.x + tid;      // over B*T1
    int b = g >> 13, t = g & (T1-1);
    const float* xp = x + b*T0;
    float xv[15];
    int base = 2*t - 7;
    #pragma unroll
    for (int k = 0; k < 15; k++){ int p = base + k; xv[k] = (p >= 0 && p < T0) ? xp[p] : 0.f; }
    float* op = g_h1 + b*H*T1 + t;
    #pragma unroll
    for (int c = 0; c < H; c++){
        float a = 0.f;
        #pragma unroll
        for (int k = 0; k < 15; k++) a = fmaf(sw[c*15+k], xv[k], a);
        op[c*T1] = lrelu(a + sb[c]);
    }
}

// ---------------- conv2: 32->64, K=15, stride 2, pad 7 (fp32, k-outer order) ----------------
#define CONV2_SM ((32*272 + 30720 + 64)*4)
__global__ void k_conv2(const float* __restrict__ w, const float* __restrict__ bias){
    extern __shared__ float sm[];
    float* sIn = sm;               // 32 x 272 (span 269)
    float* sW  = sm + 32*272;      // 64*32*15
    float* sb  = sW + 30720;       // 64
    int tid = threadIdx.x;
    int b  = blockIdx.y;
    int t0 = blockIdx.x*128;
    for (int i = tid; i < 30720; i += 256) sW[i] = w[i];
    if (tid < 64) sb[tid] = bias[tid];
    int pbase = 2*t0 - 7;
    for (int i = tid; i < 32*269; i += 256){
        int ci = i/269, s = i - ci*269;
        int p  = pbase + s;
        sIn[ci*272+s] = (p >= 0 && p < T1) ? g_h1[(b*32+ci)*T1 + p] : 0.f;
    }
    __syncthreads();
    int tx = tid & 31, ty = tid >> 5;
    int co0 = ty*8;
    float acc[8][4];
    #pragma unroll
    for (int u = 0; u < 8; u++)
        #pragma unroll
        for (int j = 0; j < 4; j++) acc[u][j] = 0.f;
    // re-roll variant: k outer, ci inner
    #pragma unroll 3
    for (int k = 0; k < 15; k++){
        for (int ci = 0; ci < 32; ci++){
            float wv[8];
            #pragma unroll
            for (int u = 0; u < 8; u++) wv[u] = sW[((co0+u)*32+ci)*15 + k];
            #pragma unroll
            for (int j = 0; j < 4; j++){
                float xv = sIn[ci*272 + 2*(tx+32*j) + k];
                #pragma unroll
                for (int u = 0; u < 8; u++) acc[u][j] = fmaf(wv[u], xv, acc[u][j]);
            }
        }
    }
    #pragma unroll
    for (int u = 0; u < 8; u++){
        int co = co0 + u;
        float bb = sb[co];
        #pragma unroll
        for (int j = 0; j < 4; j++){
            int t = t0 + tx + 32*j;
            g_h2[(b*64+co)*T2 + t] = lrelu(acc[u][j] + bb);
        }
    }
}

// ---------------- conv3: 64->64, K=3, stride 1, pad 1 (fp32, k-outer order) ----------------
#define CONV3_SM ((64*132 + 12288 + 64)*4)
__global__ void k_conv3(const float* __restrict__ w, const float* __restrict__ bias){
    extern __shared__ float sm[];
    float* sIn = sm;               // 64 x 132 (span 130)
    float* sW  = sm + 64*132;      // 64*64*3
    float* sb  = sW + 12288;
    int tid = threadIdx.x;
    int b  = blockIdx.y;
    int t0 = blockIdx.x*128;
    for (int i = tid; i < 12288; i += 256) sW[i] = w[i];
    if (tid < 64) sb[tid] = bias[tid];
    int pbase = t0 - 1;
    for (int i = tid; i < 64*130; i += 256){
        int ci = i/130, s = i - ci*130;
        int p  = pbase + s;
        sIn[ci*132+s] = (p >= 0 && p < T2) ? g_h2[(b*64+ci)*T2 + p] : 0.f;
    }
    __syncthreads();
    int tx = tid & 31, ty = tid >> 5;
    int co0 = ty*8;
    float acc[8][4];
    #pragma unroll
    for (int u = 0; u < 8; u++)
        #pragma unroll
        for (int j = 0; j < 4; j++) acc[u][j] = 0.f;
    // re-roll variant: k outer, ci inner
    #pragma unroll
    for (int k = 0; k < 3; k++){
        for (int ci = 0; ci < 64; ci++){
            float wv[8];
            #pragma unroll
            for (int u = 0; u < 8; u++) wv[u] = sW[((co0+u)*64+ci)*3 + k];
            #pragma unroll
            for (int j = 0; j < 4; j++){
                float xv = sIn[ci*132 + tx + 32*j + k];
                #pragma unroll
                for (int u = 0; u < 8; u++) acc[u][j] = fmaf(wv[u], xv, acc[u][j]);
            }
        }
    }
    #pragma unroll
    for (int u = 0; u < 8; u++){
        int co = co0 + u;
        float bb = sb[co];
        #pragma unroll
        for (int j = 0; j < 4; j++){
            int t = t0 + tx + 32*j;
            g_z[(b*64+co)*T2 + t] = acc[u][j] + bb;
        }
    }
}

// ---------------- codebook norms: XLA row-reduce emulation ----------------
__global__ void k_cnorm(const float* __restrict__ cb){
    int wid = (blockIdx.x*256 + threadIdx.x) >> 5;   // code row, 1024 total
    int lid = threadIdx.x & 31;
    float2 v = *(const float2*)&cb[wid*64 + 2*lid];
    float p = __fmul_rn(v.x, v.x);
    p = __fadd_rn(p, __fmul_rn(v.y, v.y));
    p = warp_tree_sum(p);
    if (lid == 0) g_cn[wid] = p;
}

// ---------------- z row norms: XLA row-reduce emulation ----------------
__global__ void k_zn(){
    __shared__ float st[64*33];
    int tid = threadIdx.x;
    int b  = blockIdx.x >> 7;            // 128 blocks per b
    int t0 = (blockIdx.x & 127)*32;
    for (int i = tid; i < 64*32; i += 256){
        int d = i >> 5, tt = i & 31;
        st[d*33+tt] = g_z[(b*64+d)*T2 + t0 + tt];
    }
    __syncthreads();
    int w = tid >> 5, lid = tid & 31;
    #pragma unroll
    for (int pass = 0; pass < 4; pass++){
        int tt = pass*8 + w;
        float v0 = st[(2*lid  )*33 + tt];
        float v1 = st[(2*lid+1)*33 + tt];
        float p = __fmul_rn(v0, v0);
        p = __fadd_rn(p, __fmul_rn(v1, v1));
        p = warp_tree_sum(p);
        if (lid == 0) g_zn[b*T2 + t0 + tt] = p;
    }
}

// ---------------- VQ argmin: 128 rows/block, 1024 codes ----------------
// dist = fl(fl(zn+cn) - 2*dot), pure fp32; ties -> lowest index.
#define VQ_SM ((8192 + 128 + 16384 + 256)*4)
__global__ void k_vq(const float* __restrict__ cb, float* __restrict__ out_idxf){
    extern __shared__ float sm[];
    float* sZ  = sm;               // [d][row] 64x128 (transposed)
    float* szn = sm + 8192;        // 128 row norms
    float* sCb = szn + 128;        // 256 codes x 64 (natural layout)
    float* scn = sCb + 16384;      // 256 code norms
    float* redD = sCb;             // reuse after chunks
    int*   redI = (int*)(sCb + 1024);
    int tid = threadIdx.x;
    int row0 = blockIdx.x*128;
    int b  = row0 >> 12;
    int t0 = row0 & 4095;
    for (int i = tid; i < 8192; i += 256){
        int d = i >> 7, rr = i & 127;
        sZ[i] = g_z[(b*64+d)*T2 + t0 + rr];
    }
    if (tid < 128) szn[tid] = g_zn[row0 + tid];
    __syncthreads();
    int rgrp = tid & 31, cgrp = tid >> 5;
    int rb = rgrp*4;
    float zn[4];
    #pragma unroll
    for (int i = 0; i < 4; i++) zn[i] = szn[rb+i];
    float bd[4] = {3.4e38f, 3.4e38f, 3.4e38f, 3.4e38f};
    int   bi[4] = {0,0,0,0};
    for (int ch = 0; ch < 4; ch++){
        for (int i = tid; i < 16384; i += 256) sCb[i] = cb[ch*16384 + i];
        if (tid < 256) scn[tid] = g_cn[ch*256 + tid];
        __syncthreads();
        for (int v = 0; v < 8; v++){
            int c0 = cgrp*32 + v*4;
            float a[4][4];
            #pragma unroll
            for (int i = 0; i < 4; i++)
                #pragma unroll
                for (int j = 0; j < 4; j++) a[i][j] = 0.f;
            const float* cp0 = &sCb[(c0+0)*64];
            const float* cp1 = &sCb[(c0+1)*64];
            const float* cp2 = &sCb[(c0+2)*64];
            const float* cp3 = &sCb[(c0+3)*64];
            #pragma unroll 4
            for (int d = 0; d < 64; d++){
                float4 zv = *(const float4*)&sZ[d*128 + rb];
                float c0v = cp0[d], c1v = cp1[d], c2v = cp2[d], c3v = cp3[d];
                a[0][0] = fmaf(zv.x, c0v, a[0][0]); a[1][0] = fmaf(zv.y, c0v, a[1][0]);
                a[2][0] = fmaf(zv.z, c0v, a[2][0]); a[3][0] = fmaf(zv.w, c0v, a[3][0]);
                a[0][1] = fmaf(zv.x, c1v, a[0][1]); a[1][1] = fmaf(zv.y, c1v, a[1][1]);
                a[2][1] = fmaf(zv.z, c1v, a[2][1]); a[3][1] = fmaf(zv.w, c1v, a[3][1]);
                a[0][2] = fmaf(zv.x, c2v, a[0][2]); a[1][2] = fmaf(zv.y, c2v, a[1][2]);
                a[2][2] = fmaf(zv.z, c2v, a[2][2]); a[3][2] = fmaf(zv.w, c2v, a[3][2]);
                a[0][3] = fmaf(zv.x, c3v, a[0][3]); a[1][3] = fmaf(zv.y, c3v, a[1][3]);
                a[2][3] = fmaf(zv.z, c3v, a[2][3]); a[3][3] = fmaf(zv.w, c3v, a[3][3]);
            }
            #pragma unroll
            for (int j = 0; j < 4; j++){
                int gc = ch*256 + c0 + j;
                float cn = scn[c0+j];
                #pragma unroll
                for (int i = 0; i < 4; i++){
                    float s = __fadd_rn(zn[i], cn);
                    float dist = __fsub_rn(s, __fmul_rn(2.0f, a[i][j]));
                    if (dist < bd[i]){ bd[i] = dist; bi[i] = gc; }
                }
            }
        }
        __syncthreads();
    }
    #pragma unroll
    for (int i = 0; i < 4; i++){ redD[cgrp*128 + rb + i] = bd[i]; redI[cgrp*128 + rb + i] = bi[i]; }
    __syncthreads();
    if (tid < 128){
        float d0 = redD[tid]; int i0 = redI[tid];
        #pragma unroll
        for (int g2 = 1; g2 < 8; g2++){
            float dg = redD[g2*128 + tid]; int ig = redI[g2*128 + tid];
            if (dg < d0 || (dg == d0 && ig < i0)){ d0 = dg; i0 = ig; }
        }
        g_idx[row0 + tid] = i0;
        out_idxf[row0 + tid] = (float)i0;
    }
}

// ---------------- gather quant, loss partials, q_st for decoder ----------------
__global__ void k_gather(const float* __restrict__ cb){
    __shared__ float red[256];
    int e = blockIdx.x*256 + threadIdx.x;           // over B*ZD*T2 = 8388608
    int b = e >> 18, rem = e & 262143, d = rem >> 12, t = rem & 4095;
    int id = g_idx[(b << 12) + t];
    float q = cb[id*64 + d];
    float z = g_z[e];
    float df = __fsub_rn(q, z);
    g_quant[e] = __fadd_rn(z, df);                  // q_st (reference rounding)
    red[threadIdx.x] = __fmul_rn(df, df);
    __syncthreads();
    for (int s = 128; s > 0; s >>= 1){
        if (threadIdx.x < s) red[threadIdx.x] += red[threadIdx.x + s];
        __syncthreads();
    }
    if (threadIdx.x == 0) g_part[blockIdx.x] = red[0];
}

__global__ void k_loss(float* __restrict__ out){
    __shared__ float red[256];
    int tid = threadIdx.x;
    float a = 0.f;
    for (int i = tid; i < 32768; i += 256) a += g_part[i];
    red[tid] = a; __syncthreads();
    for (int s = 128; s > 0; s >>= 1){
        if (tid < s) red[tid] += red[tid + s];
        __syncthreads();
    }
    if (tid == 0) out[B*T0] = 1.25f * red[0] / 8388608.0f;
}

// ---------------- deconv1: ConvT 64->64, K=4, stride 2, pad 1 (fp32) ----------------
#define DC1_SM ((64*68 + 16384 + 64)*4)
__global__ void k_deconv1(const float* __restrict__ w, const float* __restrict__ bias){
    extern __shared__ float sm[];
    float* sIn = sm;               // 64 x 68 (span 66: m0-1..m0+64)
    float* sW  = sm + 64*68;       // 64*64*4
    float* sb  = sW + 16384;
    int tid = threadIdx.x;
    int b  = blockIdx.y;
    int m0 = blockIdx.x*64;
    for (int i = tid; i < 16384; i += 256) sW[i] = w[i];
    if (tid < 64) sb[tid] = bias[tid];
    for (int i = tid; i < 64*66; i += 256){
        int ci = i/66, s = i - ci*66;
        int t = m0 - 1 + s;
        sIn[ci*68+s] = (t >= 0 && t < T2) ? g_quant[(b*64+ci)*T2 + t] : 0.f;
    }
    __syncthreads();
    int tx = tid & 31, ty = tid >> 5;
    int co0 = ty*8;
    float ye[8][2], yo[8][2];
    #pragma unroll
    for (int u = 0; u < 8; u++)
        #pragma unroll
        for (int j = 0; j < 2; j++){ ye[u][j] = 0.f; yo[u][j] = 0.f; }
    for (int i = 0; i < 64; i++){
        float xm1[2], xm[2], xp1[2];
        #pragma unroll
        for (int j = 0; j < 2; j++){
            int s = tx + 32*j;
            xm1[j] = sIn[i*68 + s];
            xm [j] = sIn[i*68 + s + 1];
            xp1[j] = sIn[i*68 + s + 2];
        }
        #pragma unroll
        for (int u = 0; u < 8; u++){
            float4 wv = *(const float4*)&sW[(i*64 + co0 + u)*4];
            #pragma unroll
            for (int j = 0; j < 2; j++){
                ye[u][j] = fmaf(xm [j], wv.y, ye[u][j]);
                ye[u][j] = fmaf(xm1[j], wv.w, ye[u][j]);
                yo[u][j] = fmaf(xp1[j], wv.x, yo[u][j]);
                yo[u][j] = fmaf(xm [j], wv.z, yo[u][j]);
            }
        }
    }
    #pragma unroll
    for (int u = 0; u < 8; u++){
        float bb = sb[co0+u];
        #pragma unroll
        for (int j = 0; j < 2; j++){
            int m = m0 + tx + 32*j;
            float2 o;
            o.x = lrelu(ye[u][j] + bb);
            o.y = lrelu(yo[u][j] + bb);
            *(float2*)&g_d1[(b*64 + co0 + u)*T1 + 2*m] = o;
        }
    }
}

// ---------------- deconv2: ConvT 64->32, K=4, stride 2, pad 1 (fp32) ----------------
#define DC2_SM ((64*132 + 8192 + 32)*4)
__global__ void k_deconv2(const float* __restrict__ w, const float* __restrict__ bias){
    extern __shared__ float sm[];
    float* sIn = sm;               // 64 x 132 (span 130: m0-1..m0+128)
    float* sW  = sm + 64*132;      // 64*32*4
    float* sb  = sW + 8192;
    int tid = threadIdx.x;
    int b  = blockIdx.y;
    int m0 = blockIdx.x*128;
    for (int i = tid; i < 8192; i += 256) sW[i] = w[i];
    if (tid < 32) sb[tid] = bias[tid];
    for (int i = tid; i < 64*130; i += 256){
        int ci = i/130, s = i - ci*130;
        int t = m0 - 1 + s;
        sIn[ci*132+s] = (t >= 0 && t < T1) ? g_d1[(b*64+ci)*T1 + t] : 0.f;
    }
    __syncthreads();
    int tx = tid & 31, ty = tid >> 5;
    int co0 = ty*4;
    float ye[4][4], yo[4][4];
    #pragma unroll
    for (int u = 0; u < 4; u++)
        #pragma unroll
        for (int j = 0; j < 4; j++){ ye[u][j] = 0.f; yo[u][j] = 0.f; }
    for (int i = 0; i < 64; i++){
        float xm1[4], xm[4], xp1[4];
        #pragma unroll
        for (int j = 0; j < 4; j++){
            int s = tx + 32*j;
            xm1[j] = sIn[i*132 + s];
            xm [j] = sIn[i*132 + s + 1];
            xp1[j] = sIn[i*132 + s + 2];
        }
        #pragma unroll
        for (int u = 0; u < 4; u++){
            float4 wv = *(const float4*)&sW[(i*32 + co0 + u)*4];
            #pragma unroll
            for (int j = 0; j < 4; j++){
                ye[u][j] = fmaf(xm [j], wv.y, ye[u][j]);
                ye[u][j] = fmaf(xm1[j], wv.w, ye[u][j]);
                yo[u][j] = fmaf(xp1[j], wv.x, yo[u][j]);
                yo[u][j] = fmaf(xm [j], wv.z, yo[u][j]);
            }
        }
    }
    #pragma unroll
    for (int u = 0; u < 4; u++){
        float bb = sb[co0+u];
        #pragma unroll
        for (int j = 0; j < 4; j++){
            int m = m0 + tx + 32*j;
            float2 o;
            o.x = lrelu(ye[u][j] + bb);
            o.y = lrelu(yo[u][j] + bb);
            *(float2*)&g_d2[(b*32 + co0 + u)*T0 + 2*m] = o;
        }
    }
}

// ---------------- out conv: 32->1, K=7, pad 3, tanh (fp32) ----------------
#define OUT_SM ((32*264 + 224)*4)
__global__ void k_out(const float* __restrict__ w, const float* __restrict__ bias,
                      float* __restrict__ out){
    extern __shared__ float sm[];
    float* sIn = sm;               // 32 x 264 (span 262)
    float* sw  = sm + 32*264;      // 224
    __shared__ float sb0;
    int tid = threadIdx.x;
    int b  = blockIdx.y;
    int t0 = blockIdx.x*256;
    for (int i = tid; i < 224; i += 256) sw[i] = w[i];
    if (tid == 0) sb0 = bias[0];
    for (int i = tid; i < 32*262; i += 256){
        int ci = i/262, s = i - ci*262;
        int p  = t0 - 3 + s;
        sIn[ci*264+s] = (p >= 0 && p < T0) ? g_d2[(b*32+ci)*T0 + p] : 0.f;
    }
    __syncthreads();
    float a = 0.f;
    for (int ci = 0; ci < 32; ci++){
        #pragma unroll
        for (int k = 0; k < 7; k++) a = fmaf(sw[ci*7+k], sIn[ci*264 + tid + k], a);
    }
    out[b*T0 + t0 + tid] = tanhf(a + sb0);
}

// ---------------- launch ----------------
extern "C" void kernel_launch(void* const* d_in, const int* in_sizes, int n_in,
                              void* d_out, int out_size){
    (void)in_sizes; (void)n_in; (void)out_size;
    const float* x   = (const float*)d_in[0];
    const float* c1w = (const float*)d_in[1];
    const float* c1b = (const float*)d_in[2];
    const float* c2w = (const float*)d_in[3];
    const float* c2b = (const float*)d_in[4];
    const float* c3w = (const float*)d_in[5];
    const float* c3b = (const float*)d_in[6];
    const float* cb  = (const float*)d_in[7];
    const float* d1w = (const float*)d_in[8];
    const float* d1b = (const float*)d_in[9];
    const float* d2w = (const float*)d_in[10];
    const float* d2b = (const float*)d_in[11];
    const float* ow  = (const float*)d_in[12];
    const float* ob  = (const float*)d_in[13];
    float* out = (float*)d_out;

    cudaFuncSetAttribute(k_conv2,   cudaFuncAttributeMaxDynamicSharedMemorySize, CONV2_SM);
    cudaFuncSetAttribute(k_conv3,   cudaFuncAttributeMaxDynamicSharedMemorySize, CONV3_SM);
    cudaFuncSetAttribute(k_vq,      cudaFuncAttributeMaxDynamicSharedMemorySize, VQ_SM);
    cudaFuncSetAttribute(k_deconv1, cudaFuncAttributeMaxDynamicSharedMemorySize, DC1_SM);
    cudaFuncSetAttribute(k_deconv2, cudaFuncAttributeMaxDynamicSharedMemorySize, DC2_SM);
    cudaFuncSetAttribute(k_out,     cudaFuncAttributeMaxDynamicSharedMemorySize, OUT_SM);

    k_conv1  <<<1024, 256>>>(x, c1w, c1b);
    k_conv2  <<<dim3(32,32), 256, CONV2_SM>>>(c2w, c2b);
    k_conv3  <<<dim3(32,32), 256, CONV3_SM>>>(c3w, c3b);
    k_cnorm  <<<128, 256>>>(cb);
    k_zn     <<<4096, 256>>>();
    k_vq     <<<1024, 256, VQ_SM>>>(cb, out + B*T0 + 1);
    k_gather <<<32768, 256>>>(cb);
    k_loss   <<<1, 256>>>(out);
    k_deconv1<<<dim3(64,32), 256, DC1_SM>>>(d1w, d1b);
    k_deconv2<<<dim3(64,32), 256, DC2_SM>>>(d2w, d2b);
    k_out    <<<dim3(64,32), 256, OUT_SM>>>(ow, ob, out);
}

// round 7
// speedup vs baseline: 1.1213x; 1.1213x over previous
#include <cuda_runtime.h>
#include <math.h>
#include <stdint.h>

#define B   32
#define T0  16384
#define T1  8192
#define T2  4096
#define H   32
#define H2  64
#define ZD  64
#define KCB 1024

// ---------------- scratch (device globals; no runtime alloc) ----------------
__device__ float g_h1[B*H*T1];        // after conv1+lrelu   [b][32][8192]
__device__ float g_h2[B*H2*T2];       // after conv2+lrelu   [b][64][4096]
__device__ float g_z [B*ZD*T2];       // after conv3         [b][64][4096]
__device__ float g_quant[B*ZD*T2];    // q_st for decoder    [b][64][4096]
__device__ int   g_idx[B*T2];         // argmin indices
__device__ float g_d1[B*H2*T1];       // after deconv1+lrelu [b][64][8192]
__device__ float g_d2[B*H*T0];        // after deconv2+lrelu [b][32][16384]
__device__ float g_cn[KCB];           // codebook squared norms
__device__ float g_zn[B*T2];          // z row norms
__device__ float g_part[32768];       // loss partial sums

__device__ __forceinline__ float lrelu(float v){ return v > 0.f ? v : 0.2f*v; }

// ---- packed fp32x2 helpers (bit-exact: each half is IEEE fp32 rn) ----
__device__ __forceinline__ void ffma2(uint64_t &d, uint64_t a, uint64_t b){
    asm("fma.rn.f32x2 %0, %1, %2, %0;" : "+l"(d) : "l"(a), "l"(b));
}
__device__ __forceinline__ uint64_t dup2(float x){
    uint64_t r; asm("mov.b64 %0, {%1, %1};" : "=l"(r) : "f"(x)); return r;
}
__device__ __forceinline__ uint64_t pack2(float lo, float hi){
    uint64_t r; asm("mov.b64 %0, {%1, %2};" : "=l"(r) : "f"(lo), "f"(hi)); return r;
}
__device__ __forceinline__ void unpk(float &lo, float &hi, uint64_t v){
    asm("mov.b64 {%0, %1}, %2;" : "=f"(lo), "=f"(hi) : "l"(v));
}

// XLA row-reduce warp tree: partial -> shfl_down 16/8/4/2/1, result in lane 0.
__device__ __forceinline__ float warp_tree_sum(float p){
    #pragma unroll
    for (int off = 16; off > 0; off >>= 1)
        p = __fadd_rn(p, __shfl_down_sync(0xFFFFFFFFu, p, off));
    return p;
}

// ---------------- conv1: 1->32, K=15, stride 2, pad 7 (fp32) ----------------
__global__ void k_conv1(const float* __restrict__ x, const float* __restrict__ w,
                        const float* __restrict__ bias){
    __shared__ float sw[H*15];
    __shared__ float sb[H];
    int tid = threadIdx.x;
    for (int i = tid; i < H*15; i += blockDim.x) sw[i] = w[i];
    if (tid < H) sb[tid] = bias[tid];
    __syncthreads();
    int g = blockIdx.x*blockDim.x + tid;      // over B*T1
    int b = g >> 13, t = g & (T1-1);
    const float* xp = x + b*T0;
    float xv[15];
    int base = 2*t - 7;
    #pragma unroll
    for (int k = 0; k < 15; k++){ int p = base + k; xv[k] = (p >= 0 && p < T0) ? xp[p] : 0.f; }
    float* op = g_h1 + b*H*T1 + t;
    #pragma unroll
    for (int c = 0; c < H; c++){
        float a = 0.f;
        #pragma unroll
        for (int k = 0; k < 15; k++) a = fmaf(sw[c*15+k], xv[k], a);
        op[c*T1] = lrelu(a + sb[c]);
    }
}

// ---------------- conv2: 32->64, K=15, stride 2, pad 7 (f32x2, k-outer order) ----------------
#define CONV2_SM ((32*272 + 30720 + 64)*4)
__global__ void k_conv2(const float* __restrict__ w, const float* __restrict__ bias){
    extern __shared__ float sm[];
    float* sIn = sm;               // 32 x 272 (span 269)
    float* sW  = sm + 32*272;      // 64*32*15
    float* sb  = sW + 30720;       // 64
    int tid = threadIdx.x;
    int b  = blockIdx.y;
    int t0 = blockIdx.x*128;
    for (int i = tid; i < 30720; i += 256) sW[i] = w[i];
    if (tid < 64) sb[tid] = bias[tid];
    int pbase = 2*t0 - 7;
    for (int i = tid; i < 32*269; i += 256){
        int ci = i/269, s = i - ci*269;
        int p  = pbase + s;
        sIn[ci*272+s] = (p >= 0 && p < T1) ? g_h1[(b*32+ci)*T1 + p] : 0.f;
    }
    __syncthreads();
    int tx = tid & 31, ty = tid >> 5;
    int co0 = ty*8;
    // packed accumulators: ap[u][p] = {acc[u][2p], acc[u][2p+1]}
    uint64_t ap[8][2];
    #pragma unroll
    for (int u = 0; u < 8; u++){ ap[u][0] = 0ull; ap[u][1] = 0ull; }
    #pragma unroll 3
    for (int k = 0; k < 15; k++){
        for (int ci = 0; ci < 32; ci++){
            uint64_t wd[8];
            #pragma unroll
            for (int u = 0; u < 8; u++) wd[u] = dup2(sW[((co0+u)*32+ci)*15 + k]);
            float x0 = sIn[ci*272 + 2*tx        + k];
            float x1 = sIn[ci*272 + 2*(tx+32)   + k];
            float x2 = sIn[ci*272 + 2*(tx+64)   + k];
            float x3 = sIn[ci*272 + 2*(tx+96)   + k];
            uint64_t px0 = pack2(x0, x1), px1 = pack2(x2, x3);
            #pragma unroll
            for (int u = 0; u < 8; u++){
                ffma2(ap[u][0], wd[u], px0);
                ffma2(ap[u][1], wd[u], px1);
            }
        }
    }
    #pragma unroll
    for (int u = 0; u < 8; u++){
        int co = co0 + u;
        float bb = sb[co];
        float a0,a1,a2,a3;
        unpk(a0, a1, ap[u][0]); unpk(a2, a3, ap[u][1]);
        g_h2[(b*64+co)*T2 + t0 + tx      ] = lrelu(a0 + bb);
        g_h2[(b*64+co)*T2 + t0 + tx + 32 ] = lrelu(a1 + bb);
        g_h2[(b*64+co)*T2 + t0 + tx + 64 ] = lrelu(a2 + bb);
        g_h2[(b*64+co)*T2 + t0 + tx + 96 ] = lrelu(a3 + bb);
    }
}

// ---------------- conv3: 64->64, K=3, stride 1, pad 1 (f32x2, k-outer order) ----------------
#define CONV3_SM ((64*132 + 12288 + 64)*4)
__global__ void k_conv3(const float* __restrict__ w, const float* __restrict__ bias){
    extern __shared__ float sm[];
    float* sIn = sm;               // 64 x 132 (span 130)
    float* sW  = sm + 64*132;      // 64*64*3
    float* sb  = sW + 12288;
    int tid = threadIdx.x;
    int b  = blockIdx.y;
    int t0 = blockIdx.x*128;
    for (int i = tid; i < 12288; i += 256) sW[i] = w[i];
    if (tid < 64) sb[tid] = bias[tid];
    int pbase = t0 - 1;
    for (int i = tid; i < 64*130; i += 256){
        int ci = i/130, s = i - ci*130;
        int p  = pbase + s;
        sIn[ci*132+s] = (p >= 0 && p < T2) ? g_h2[(b*64+ci)*T2 + p] : 0.f;
    }
    __syncthreads();
    int tx = tid & 31, ty = tid >> 5;
    int co0 = ty*8;
    uint64_t ap[8][2];
    #pragma unroll
    for (int u = 0; u < 8; u++){ ap[u][0] = 0ull; ap[u][1] = 0ull; }
    #pragma unroll
    for (int k = 0; k < 3; k++){
        for (int ci = 0; ci < 64; ci++){
            uint64_t wd[8];
            #pragma unroll
            for (int u = 0; u < 8; u++) wd[u] = dup2(sW[((co0+u)*64+ci)*3 + k]);
            float x0 = sIn[ci*132 + tx      + k];
            float x1 = sIn[ci*132 + tx + 32 + k];
            float x2 = sIn[ci*132 + tx + 64 + k];
            float x3 = sIn[ci*132 + tx + 96 + k];
            uint64_t px0 = pack2(x0, x1), px1 = pack2(x2, x3);
            #pragma unroll
            for (int u = 0; u < 8; u++){
                ffma2(ap[u][0], wd[u], px0);
                ffma2(ap[u][1], wd[u], px1);
            }
        }
    }
    #pragma unroll
    for (int u = 0; u < 8; u++){
        int co = co0 + u;
        float bb = sb[co];
        float a0,a1,a2,a3;
        unpk(a0, a1, ap[u][0]); unpk(a2, a3, ap[u][1]);
        g_z[(b*64+co)*T2 + t0 + tx      ] = a0 + bb;
        g_z[(b*64+co)*T2 + t0 + tx + 32 ] = a1 + bb;
        g_z[(b*64+co)*T2 + t0 + tx + 64 ] = a2 + bb;
        g_z[(b*64+co)*T2 + t0 + tx + 96 ] = a3 + bb;
    }
}

// ---------------- codebook norms: XLA row-reduce emulation ----------------
__global__ void k_cnorm(const float* __restrict__ cb){
    int wid = (blockIdx.x*256 + threadIdx.x) >> 5;   // code row, 1024 total
    int lid = threadIdx.x & 31;
    float2 v = *(const float2*)&cb[wid*64 + 2*lid];
    float p = __fmul_rn(v.x, v.x);
    p = __fadd_rn(p, __fmul_rn(v.y, v.y));
    p = warp_tree_sum(p);
    if (lid == 0) g_cn[wid] = p;
}

// ---------------- z row norms: XLA row-reduce emulation ----------------
__global__ void k_zn(){
    __shared__ float st[64*33];
    int tid = threadIdx.x;
    int b  = blockIdx.x >> 7;            // 128 blocks per b
    int t0 = (blockIdx.x & 127)*32;
    for (int i = tid; i < 64*32; i += 256){
        int d = i >> 5, tt = i & 31;
        st[d*33+tt] = g_z[(b*64+d)*T2 + t0 + tt];
    }
    __syncthreads();
    int w = tid >> 5, lid = tid & 31;
    #pragma unroll
    for (int pass = 0; pass < 4; pass++){
        int tt = pass*8 + w;
        float v0 = st[(2*lid  )*33 + tt];
        float v1 = st[(2*lid+1)*33 + tt];
        float p = __fmul_rn(v0, v0);
        p = __fadd_rn(p, __fmul_rn(v1, v1));
        p = warp_tree_sum(p);
        if (lid == 0) g_zn[b*T2 + t0 + tt] = p;
    }
}

// ---------------- VQ argmin: 128 rows/block, 1024 codes (f32x2 dot) ----------------
// dist = fl(fl(zn+cn) - 2*dot), pure fp32; ties -> lowest index.
// Codebook chunk transposed in smem [d][c] (stride 260); rows paired in b64.
#define CT_S 260
#define VQ_SM ((8192 + 128 + 64*CT_S + 256)*4)
__global__ void k_vq(const float* __restrict__ cb, float* __restrict__ out_idxf){
    extern __shared__ float sm[];
    float* sZ  = sm;               // [d][row] 64x128 (transposed)
    float* szn = sm + 8192;        // 128 row norms
    float* sCbT= szn + 128;        // transposed chunk [64][CT_S]
    float* scn = sCbT + 64*CT_S;   // 256 code norms
    float* redD = sCbT;            // reuse after chunks
    int*   redI = (int*)(sCbT + 1024);
    int tid = threadIdx.x;
    int row0 = blockIdx.x*128;
    int b  = row0 >> 12;
    int t0 = row0 & 4095;
    for (int i = tid; i < 8192; i += 256){
        int d = i >> 7, rr = i & 127;
        sZ[i] = g_z[(b*64+d)*T2 + t0 + rr];
    }
    if (tid < 128) szn[tid] = g_zn[row0 + tid];
    __syncthreads();
    int rgrp = tid & 31, cgrp = tid >> 5;
    int rb = rgrp*4;
    float zn[4];
    #pragma unroll
    for (int i = 0; i < 4; i++) zn[i] = szn[rb+i];
    float bd[4] = {3.4e38f, 3.4e38f, 3.4e38f, 3.4e38f};
    int   bi[4] = {0,0,0,0};
    for (int ch = 0; ch < 4; ch++){
        // fill transposed chunk: sCbT[d][c] = cb[(ch*256+c)*64 + d]
        for (int i = tid; i < 16384; i += 256){
            int d = i & 63, c = i >> 6;
            sCbT[d*CT_S + c] = cb[(ch*256+c)*64 + d];
        }
        if (tid < 256) scn[tid] = g_cn[ch*256 + tid];
        __syncthreads();
        for (int v = 0; v < 8; v++){
            int c0 = cgrp*32 + v*4;
            // pr[p][j] = {a[2p][j], a[2p+1][j]}
            uint64_t pr[2][4];
            #pragma unroll
            for (int p = 0; p < 2; p++)
                #pragma unroll
                for (int j = 0; j < 4; j++) pr[p][j] = 0ull;
            #pragma unroll 4
            for (int d = 0; d < 64; d++){
                ulonglong2 zp = *(const ulonglong2*)&sZ[d*128 + rb];   // {z0,z1},{z2,z3}
                const float4 cv = *(const float4*)&sCbT[d*CT_S + c0];  // broadcast
                uint64_t cd0 = dup2(cv.x), cd1 = dup2(cv.y), cd2 = dup2(cv.z), cd3 = dup2(cv.w);
                ffma2(pr[0][0], zp.x, cd0); ffma2(pr[1][0], zp.y, cd0);
                ffma2(pr[0][1], zp.x, cd1); ffma2(pr[1][1], zp.y, cd1);
                ffma2(pr[0][2], zp.x, cd2); ffma2(pr[1][2], zp.y, cd2);
                ffma2(pr[0][3], zp.x, cd3); ffma2(pr[1][3], zp.y, cd3);
            }
            float a[4][4];
            #pragma unroll
            for (int j = 0; j < 4; j++){
                unpk(a[0][j], a[1][j], pr[0][j]);
                unpk(a[2][j], a[3][j], pr[1][j]);
            }
            #pragma unroll
            for (int j = 0; j < 4; j++){
                int gc = ch*256 + c0 + j;
                float cn = scn[c0+j];
                #pragma unroll
                for (int i = 0; i < 4; i++){
                    float s = __fadd_rn(zn[i], cn);
                    float dist = __fsub_rn(s, __fmul_rn(2.0f, a[i][j]));
                    if (dist < bd[i]){ bd[i] = dist; bi[i] = gc; }
                }
            }
        }
        __syncthreads();
    }
    #pragma unroll
    for (int i = 0; i < 4; i++){ redD[cgrp*128 + rb + i] = bd[i]; redI[cgrp*128 + rb + i] = bi[i]; }
    __syncthreads();
    if (tid < 128){
        float d0 = redD[tid]; int i0 = redI[tid];
        #pragma unroll
        for (int g2 = 1; g2 < 8; g2++){
            float dg = redD[g2*128 + tid]; int ig = redI[g2*128 + tid];
            if (dg < d0 || (dg == d0 && ig < i0)){ d0 = dg; i0 = ig; }
        }
        g_idx[row0 + tid] = i0;
        out_idxf[row0 + tid] = (float)i0;
    }
}

// ---------------- gather quant, loss partials, q_st for decoder ----------------
__global__ void k_gather(const float* __restrict__ cb){
    __shared__ float red[256];
    int e = blockIdx.x*256 + threadIdx.x;           // over B*ZD*T2 = 8388608
    int b = e >> 18, rem = e & 262143, d = rem >> 12, t = rem & 4095;
    int id = g_idx[(b << 12) + t];
    float q = cb[id*64 + d];
    float z = g_z[e];
    float df = __fsub_rn(q, z);
    g_quant[e] = __fadd_rn(z, df);                  // q_st (reference rounding)
    red[threadIdx.x] = __fmul_rn(df, df);
    __syncthreads();
    for (int s = 128; s > 0; s >>= 1){
        if (threadIdx.x < s) red[threadIdx.x] += red[threadIdx.x + s];
        __syncthreads();
    }
    if (threadIdx.x == 0) g_part[blockIdx.x] = red[0];
}

__global__ void k_loss(float* __restrict__ out){
    __shared__ float red[256];
    int tid = threadIdx.x;
    float a = 0.f;
    for (int i = tid; i < 32768; i += 256) a += g_part[i];
    red[tid] = a; __syncthreads();
    for (int s = 128; s > 0; s >>= 1){
        if (tid < s) red[tid] += red[tid + s];
        __syncthreads();
    }
    if (tid == 0) out[B*T0] = 1.25f * red[0] / 8388608.0f;
}

// ---------------- deconv1: ConvT 64->64, K=4, stride 2, pad 1 (f32x2) ----------------
// weights pre-swizzled in smem: (w1,w0,w3,w2) so float4 -> two ready b64 pairs.
// packed acc {ye,yo}: {xm,xp1}*{w1,w0} then {xm1,xm}*{w3,w2}  (chains preserved)
#define DC1_SM ((64*68 + 16384 + 64)*4)
__global__ void k_deconv1(const float* __restrict__ w, const float* __restrict__ bias){
    extern __shared__ float sm[];
    float* sIn = sm;               // 64 x 68 (span 66: m0-1..m0+64)
    float* sW  = sm + 64*68;       // 64*64*4, k-swizzled
    float* sb  = sW + 16384;
    int tid = threadIdx.x;
    int b  = blockIdx.y;
    int m0 = blockIdx.x*64;
    for (int i = tid; i < 16384; i += 256) sW[i^1] = w[i];   // swizzle k: 0<->1, 2<->3
    if (tid < 64) sb[tid] = bias[tid];
    for (int i = tid; i < 64*66; i += 256){
        int ci = i/66, s = i - ci*66;
        int t = m0 - 1 + s;
        sIn[ci*68+s] = (t >= 0 && t < T2) ? g_quant[(b*64+ci)*T2 + t] : 0.f;
    }
    __syncthreads();
    int tx = tid & 31, ty = tid >> 5;
    int co0 = ty*8;
    uint64_t py[8][2];   // [u][j], packed {ye,yo}
    #pragma unroll
    for (int u = 0; u < 8; u++){ py[u][0] = 0ull; py[u][1] = 0ull; }
    for (int i = 0; i < 64; i++){
        uint64_t pA[2], pB[2];
        #pragma unroll
        for (int j = 0; j < 2; j++){
            int s = tx + 32*j;
            float xm1 = sIn[i*68 + s];
            float xm  = sIn[i*68 + s + 1];
            float xp1 = sIn[i*68 + s + 2];
            pA[j] = pack2(xm, xp1);
            pB[j] = pack2(xm1, xm);
        }
        #pragma unroll
        for (int u = 0; u < 8; u++){
            ulonglong2 wp = *(const ulonglong2*)&sW[(i*64 + co0 + u)*4]; // {w1,w0},{w3,w2}
            #pragma unroll
            for (int j = 0; j < 2; j++){
                ffma2(py[u][j], pA[j], wp.x);
                ffma2(py[u][j], pB[j], wp.y);
            }
        }
    }
    #pragma unroll
    for (int u = 0; u < 8; u++){
        float bb = sb[co0+u];
        #pragma unroll
        for (int j = 0; j < 2; j++){
            int m = m0 + tx + 32*j;
            float ye, yo;
            unpk(ye, yo, py[u][j]);
            float2 o;
            o.x = lrelu(ye + bb);
            o.y = lrelu(yo + bb);
            *(float2*)&g_d1[(b*64 + co0 + u)*T1 + 2*m] = o;
        }
    }
}

// ---------------- deconv2: ConvT 64->32, K=4, stride 2, pad 1 (f32x2) ----------------
#define DC2_SM ((64*132 + 8192 + 32)*4)
__global__ void k_deconv2(const float* __restrict__ w, const float* __restrict__ bias){
    extern __shared__ float sm[];
    float* sIn = sm;               // 64 x 132 (span 130: m0-1..m0+128)
    float* sW  = sm + 64*132;      // 64*32*4, k-swizzled
    float* sb  = sW + 8192;
    int tid = threadIdx.x;
    int b  = blockIdx.y;
    int m0 = blockIdx.x*128;
    for (int i = tid; i < 8192; i += 256) sW[i^1] = w[i];
    if (tid < 32) sb[tid] = bias[tid];
    for (int i = tid; i < 64*130; i += 256){
        int ci = i/130, s = i - ci*130;
        int t = m0 - 1 + s;
        sIn[ci*132+s] = (t >= 0 && t < T1) ? g_d1[(b*64+ci)*T1 + t] : 0.f;
    }
    __syncthreads();
    int tx = tid & 31, ty = tid >> 5;
    int co0 = ty*4;
    uint64_t py[4][4];   // [u][j], packed {ye,yo}
    #pragma unroll
    for (int u = 0; u < 4; u++)
        #pragma unroll
        for (int j = 0; j < 4; j++) py[u][j] = 0ull;
    for (int i = 0; i < 64; i++){
        uint64_t pA[4], pB[4];
        #pragma unroll
        for (int j = 0; j < 4; j++){
            int s = tx + 32*j;
            float xm1 = sIn[i*132 + s];
            float xm  = sIn[i*132 + s + 1];
            float xp1 = sIn[i*132 + s + 2];
            pA[j] = pack2(xm, xp1);
            pB[j] = pack2(xm1, xm);
        }
        #pragma unroll
        for (int u = 0; u < 4; u++){
            ulonglong2 wp = *(const ulonglong2*)&sW[(i*32 + co0 + u)*4]; // {w1,w0},{w3,w2}
            #pragma unroll
            for (int j = 0; j < 4; j++){
                ffma2(py[u][j], pA[j], wp.x);
                ffma2(py[u][j], pB[j], wp.y);
            }
        }
    }
    #pragma unroll
    for (int u = 0; u < 4; u++){
        float bb = sb[co0+u];
        #pragma unroll
        for (int j = 0; j < 4; j++){
            int m = m0 + tx + 32*j;
            float ye, yo;
            unpk(ye, yo, py[u][j]);
            float2 o;
            o.x = lrelu(ye + bb);
            o.y = lrelu(yo + bb);
            *(float2*)&g_d2[(b*32 + co0 + u)*T0 + 2*m] = o;
        }
    }
}

// ---------------- out conv: 32->1, K=7, pad 3, tanh (fp32) ----------------
#define OUT_SM ((32*264 + 224)*4)
__global__ void k_out(const float* __restrict__ w, const float* __restrict__ bias,
                      float* __restrict__ out){
    extern __shared__ float sm[];
    float* sIn = sm;               // 32 x 264 (span 262)
    float* sw  = sm + 32*264;      // 224
    __shared__ float sb0;
    int tid = threadIdx.x;
    int b  = blockIdx.y;
    int t0 = blockIdx.x*256;
    for (int i = tid; i < 224; i += 256) sw[i] = w[i];
    if (tid == 0) sb0 = bias[0];
    for (int i = tid; i < 32*262; i += 256){
        int ci = i/262, s = i - ci*262;
        int p  = t0 - 3 + s;
        sIn[ci*264+s] = (p >= 0 && p < T0) ? g_d2[(b*32+ci)*T0 + p] : 0.f;
    }
    __syncthreads();
    float a = 0.f;
    for (int ci = 0; ci < 32; ci++){
        #pragma unroll
        for (int k = 0; k < 7; k++) a = fmaf(sw[ci*7+k], sIn[ci*264 + tid + k], a);
    }
    out[b*T0 + t0 + tid] = tanhf(a + sb0);
}

// ---------------- launch ----------------
extern "C" void kernel_launch(void* const* d_in, const int* in_sizes, int n_in,
                              void* d_out, int out_size){
    (void)in_sizes; (void)n_in; (void)out_size;
    const float* x   = (const float*)d_in[0];
    const float* c1w = (const float*)d_in[1];
    const float* c1b = (const float*)d_in[2];
    const float* c2w = (const float*)d_in[3];
    const float* c2b = (const float*)d_in[4];
    const float* c3w = (const float*)d_in[5];
    const float* c3b = (const float*)d_in[6];
    const float* cb  = (const float*)d_in[7];
    const float* d1w = (const float*)d_in[8];
    const float* d1b = (const float*)d_in[9];
    const float* d2w = (const float*)d_in[10];
    const float* d2b = (const float*)d_in[11];
    const float* ow  = (const float*)d_in[12];
    const float* ob  = (const float*)d_in[13];
    float* out = (float*)d_out;

    cudaFuncSetAttribute(k_conv2,   cudaFuncAttributeMaxDynamicSharedMemorySize, CONV2_SM);
    cudaFuncSetAttribute(k_conv3,   cudaFuncAttributeMaxDynamicSharedMemorySize, CONV3_SM);
    cudaFuncSetAttribute(k_vq,      cudaFuncAttributeMaxDynamicSharedMemorySize, VQ_SM);
    cudaFuncSetAttribute(k_deconv1, cudaFuncAttributeMaxDynamicSharedMemorySize, DC1_SM);
    cudaFuncSetAttribute(k_deconv2, cudaFuncAttributeMaxDynamicSharedMemorySize, DC2_SM);
    cudaFuncSetAttribute(k_out,     cudaFuncAttributeMaxDynamicSharedMemorySize, OUT_SM);

    k_conv1  <<<1024, 256>>>(x, c1w, c1b);
    k_conv2  <<<dim3(32,32), 256, CONV2_SM>>>(c2w, c2b);
    k_conv3  <<<dim3(32,32), 256, CONV3_SM>>>(c3w, c3b);
    k_cnorm  <<<128, 256>>>(cb);
    k_zn     <<<4096, 256>>>();
    k_vq     <<<1024, 256, VQ_SM>>>(cb, out + B*T0 + 1);
    k_gather <<<32768, 256>>>(cb);
    k_loss   <<<1, 256>>>(out);
    k_deconv1<<<dim3(64,32), 256, DC1_SM>>>(d1w, d1b);
    k_deconv2<<<dim3(64,32), 256, DC2_SM>>>(d2w, d2b);
    k_out    <<<dim3(64,32), 256, OUT_SM>>>(ow, ob, out);
}